// round 1
// baseline (speedup 1.0000x reference)
#include <cuda_runtime.h>
#include <math.h>

// Problem constants (fixed by the dataset)
#define NTOK 16384
#define HDIM 4096
#define NEXP 64
#define TOPK 2

#define BM 64        // token rows per block
#define BK 64        // k-chunk
#define THREADS 256
#define WS_STRIDE 68 // padded expert-row stride for transposed W tile (16B aligned, conflict-aware)
#define LT_STRIDE 65 // padded logits-tile stride (odd -> conflict-free per-row scans)

__global__ __launch_bounds__(THREADS, 2)
void router_kernel(const float* __restrict__ x,
                   const float* __restrict__ W,
                   float* __restrict__ out_scores,
                   float* __restrict__ out_w,
                   float* __restrict__ out_e) {
    __shared__ float xs[BM * BK];            // x tile, row-major [row][k]
    __shared__ float ws[BK * WS_STRIDE];     // W tile, k-major   [k][e] (transposed)
    __shared__ float lt[BM * LT_STRIDE];     // logits tile [row][e]
    __shared__ float rmax[BM];
    __shared__ float rinv[BM];

    const int tid = threadIdx.x;
    const int tx = tid & 15;   // expert group: experts tx*4 .. tx*4+3
    const int ty = tid >> 4;   // row group:    rows    ty*4 .. ty*4+3
    const int rowBase = blockIdx.x * BM;

    float acc[4][4];
#pragma unroll
    for (int i = 0; i < 4; i++)
#pragma unroll
        for (int j = 0; j < 4; j++) acc[i][j] = 0.0f;

    for (int kt = 0; kt < HDIM; kt += BK) {
        // ---- load tiles: 64 rows x 16 float4 = 1024 float4 each ----
#pragma unroll
        for (int n = 0; n < 4; n++) {
            int i4  = tid + n * THREADS;   // 0..1023
            int row = i4 >> 4;             // 0..63
            int c4  = i4 & 15;             // float4 column in k
            // x tile (row-major, contiguous store)
            float4 xv = *(const float4*)&x[(size_t)(rowBase + row) * HDIM + kt + c4 * 4];
            *(float4*)&xs[row * BK + c4 * 4] = xv;
            // W tile (store transposed: ws[k][e])
            float4 wv = *(const float4*)&W[(size_t)row * HDIM + kt + c4 * 4]; // row = expert
            ws[(c4 * 4 + 0) * WS_STRIDE + row] = wv.x;
            ws[(c4 * 4 + 1) * WS_STRIDE + row] = wv.y;
            ws[(c4 * 4 + 2) * WS_STRIDE + row] = wv.z;
            ws[(c4 * 4 + 3) * WS_STRIDE + row] = wv.w;
        }
        __syncthreads();

        // ---- 4x4 register-tile FMA over this k-chunk ----
#pragma unroll
        for (int k4 = 0; k4 < BK / 4; k4++) {
            float4 xv[4], wv[4];
#pragma unroll
            for (int i = 0; i < 4; i++)
                xv[i] = *(const float4*)&xs[(ty * 4 + i) * BK + k4 * 4];
#pragma unroll
            for (int kc = 0; kc < 4; kc++)
                wv[kc] = *(const float4*)&ws[(k4 * 4 + kc) * WS_STRIDE + tx * 4];
#pragma unroll
            for (int i = 0; i < 4; i++) {
                const float* xp = (const float*)&xv[i];
#pragma unroll
                for (int kc = 0; kc < 4; kc++) {
                    float xk = xp[kc];
                    acc[i][0] = fmaf(xk, wv[kc].x, acc[i][0]);
                    acc[i][1] = fmaf(xk, wv[kc].y, acc[i][1]);
                    acc[i][2] = fmaf(xk, wv[kc].z, acc[i][2]);
                    acc[i][3] = fmaf(xk, wv[kc].w, acc[i][3]);
                }
            }
        }
        __syncthreads();
    }

    // ---- spill logits tile to smem ----
#pragma unroll
    for (int i = 0; i < 4; i++)
#pragma unroll
        for (int j = 0; j < 4; j++)
            lt[(ty * 4 + i) * LT_STRIDE + (tx * 4 + j)] = acc[i][j];
    __syncthreads();

    // ---- per-row softmax stats + top-2 (one thread per row) ----
    if (tid < BM) {
        const float* row = &lt[tid * LT_STRIDE];
        float m1 = -INFINITY, m2 = -INFINITY;
        int i1 = 0, i2 = 0;
#pragma unroll 8
        for (int e = 0; e < NEXP; e++) {
            float v = row[e];
            if (v > m1) { m2 = m1; i2 = i1; m1 = v; i1 = e; }
            else if (v > m2) { m2 = v; i2 = e; }
        }
        float s = 0.0f;
#pragma unroll 8
        for (int e = 0; e < NEXP; e++) s += expf(row[e] - m1);
        rmax[tid] = m1;
        rinv[tid] = 1.0f / s;

        // normalized top-2 weights: softmax(top2) / sum == e^(z-m) / (1 + e^(m2-m1))
        float e2 = expf(m2 - m1);
        float dn = 1.0f / (1.0f + e2);
        int gr = rowBase + tid;
        out_w[gr * TOPK + 0] = dn;
        out_w[gr * TOPK + 1] = e2 * dn;
        out_e[gr * TOPK + 0] = (float)i1;
        out_e[gr * TOPK + 1] = (float)i2;
    }
    __syncthreads();

    // ---- write full softmax scores (coalesced) ----
    for (int i = tid; i < BM * NEXP; i += THREADS) {
        int r = i >> 6, c = i & 63;
        out_scores[(size_t)(rowBase + r) * NEXP + c] =
            expf(lt[r * LT_STRIDE + c] - rmax[r]) * rinv[r];
    }
}

extern "C" void kernel_launch(void* const* d_in, const int* in_sizes, int n_in,
                              void* d_out, int out_size) {
    const float* x = (const float*)d_in[0];   // [N, H] f32
    const float* W = (const float*)d_in[1];   // [E, H] f32
    // d_in[2] = top_k (fixed at 2)

    float* out_scores = (float*)d_out;                      // N*E
    float* out_w      = out_scores + (size_t)NTOK * NEXP;   // N*TOPK
    float* out_e      = out_w + (size_t)NTOK * TOPK;        // N*TOPK (value-cast indices)

    router_kernel<<<NTOK / BM, THREADS>>>(x, W, out_scores, out_w, out_e);
}

// round 3
// speedup vs baseline: 4.4482x; 4.4482x over previous
#include <cuda_runtime.h>
#include <cuda_bf16.h>
#include <cstdint>

#define NTOK 16384
#define HDIM 4096
#define NEXP 64
#define TOPK 2

#define BM 128
#define BK 64
#define NCHUNK (HDIM / BK)    // 64
#define NSTAGE 3
#define THREADS 256

// x tile: 128 rows x 256B (64 f32), float2 units XOR-swizzled within row
#define XTILE_B (BM * 256)              // 32768
// W tiles: 64 rows x 36 4B-units (32 data + 4 pad) = 144B row
#define WROW_B 144
#define WTILE_B (NEXP * WROW_B)         // 9216
#define OFF_WH XTILE_B
#define OFF_WL (XTILE_B + WTILE_B)
#define STAGE_B (XTILE_B + 2 * WTILE_B) // 51200
#define SMEM_B (NSTAGE * STAGE_B)       // 153600

__device__ __nv_bfloat16 g_Wh[NEXP * HDIM];
__device__ __nv_bfloat16 g_Wl[NEXP * HDIM];

__device__ __forceinline__ uint32_t smem_u32(const void* p) {
    uint32_t a;
    asm("{ .reg .u64 t; cvta.to.shared.u64 t, %1; cvt.u32.u64 %0, t; }" : "=r"(a) : "l"(p));
    return a;
}

__device__ __forceinline__ void cpa16(uint32_t dst, const void* src) {
    asm volatile("cp.async.cg.shared.global [%0], [%1], 16;" :: "r"(dst), "l"(src) : "memory");
}

// split f32 pair into bf16x2 hi + bf16x2 lo (element0 in lo16)
__device__ __forceinline__ void split_pair(float f0, float f1, uint32_t& hi, uint32_t& lo) {
    asm("cvt.rn.bf16x2.f32 %0, %1, %2;" : "=r"(hi) : "f"(f1), "f"(f0));
    float h0 = __uint_as_float(hi << 16);
    float h1 = __uint_as_float(hi & 0xFFFF0000u);
    float l0 = f0 - h0;
    float l1 = f1 - h1;
    asm("cvt.rn.bf16x2.f32 %0, %1, %2;" : "=r"(lo) : "f"(l1), "f"(l0));
}

__device__ __forceinline__ void mma_bf16(float* d, const uint32_t* a, const uint32_t* b) {
    asm volatile(
        "mma.sync.aligned.m16n8k16.row.col.f32.bf16.bf16.f32 "
        "{%0,%1,%2,%3}, {%4,%5,%6,%7}, {%8,%9}, {%0,%1,%2,%3};"
        : "+f"(d[0]), "+f"(d[1]), "+f"(d[2]), "+f"(d[3])
        : "r"(a[0]), "r"(a[1]), "r"(a[2]), "r"(a[3]), "r"(b[0]), "r"(b[1]));
}

__global__ void wsplit_kernel(const float* __restrict__ W) {
    int i = blockIdx.x * blockDim.x + threadIdx.x;
    float w = W[i];
    __nv_bfloat16 h = __float2bfloat16(w);
    g_Wh[i] = h;
    g_Wl[i] = __float2bfloat16(w - __bfloat162float(h));
}

__device__ __forceinline__ void issue_chunk(uint32_t sbase, const float* __restrict__ x,
                                            int rowBase, int c, int tid) {
    const int s = c % NSTAGE;
    const uint32_t stb = sbase + s * STAGE_B;
    const int k0 = c * BK;
#pragma unroll
    for (int j = 0; j < 8; j++) {            // x: 2048 16B units
        int i = tid + j * THREADS;
        int row = i >> 4, q = i & 15;
        uint32_t d = stb + row * 256 + ((((2 * q) ^ ((row & 3) << 2))) << 3);
        cpa16(d, x + (size_t)(rowBase + row) * HDIM + k0 + q * 4);
    }
#pragma unroll
    for (int j = 0; j < 2; j++) {            // Wh + Wl: 512 units each
        int i = tid + j * THREADS;
        int row = i >> 3, q = i & 7;
        cpa16(stb + OFF_WH + row * WROW_B + q * 16, g_Wh + (size_t)row * HDIM + k0 + q * 8);
        cpa16(stb + OFF_WL + row * WROW_B + q * 16, g_Wl + (size_t)row * HDIM + k0 + q * 8);
    }
    asm volatile("cp.async.commit_group;" ::: "memory");
}

__global__ __launch_bounds__(THREADS, 1)
void router_mma(const float* __restrict__ x,
                float* __restrict__ out_scores,
                float* __restrict__ out_w,
                float* __restrict__ out_e) {
    extern __shared__ char smem[];
    const uint32_t sbase = smem_u32(smem);
    const int tid = threadIdx.x;
    const int lane = tid & 31;
    const int wid = tid >> 5;
    const int g = lane >> 2;        // 0..7
    const int t = lane & 3;         // 0..3
    const int wExp = wid & 1;       // expert half
    const int wTok = wid >> 1;      // token quarter
    const int rowBase = blockIdx.x * BM;
    const int tokRow0 = wTok * 32;
    const int expCol0 = wExp * 32;
    const uint32_t xorv = (uint32_t)((g & 3) << 2);

    float acc[2][4][4] = {};

    issue_chunk(sbase, x, rowBase, 0, tid);
    issue_chunk(sbase, x, rowBase, 1, tid);

    for (int c = 0; c < NCHUNK; c++) {
        const int s = c % NSTAGE;
        if (c == NCHUNK - 1) {
            asm volatile("cp.async.wait_group 0;" ::: "memory");
        } else {
            asm volatile("cp.async.wait_group 1;" ::: "memory");
        }
        __syncthreads();

        const char* st = smem + s * STAGE_B;
        const char* xs = st;
        const char* wh = st + OFF_WH;
        const char* wl = st + OFF_WL;

#pragma unroll
        for (int ks = 0; ks < 4; ks++) {
            // B fragments (W hi/lo, conflict-free stride-36)
            uint32_t bh[4][2], bl[4][2];
#pragma unroll
            for (int nt = 0; nt < 4; nt++) {
                int n = expCol0 + nt * 8 + g;
                const char* whn = wh + n * WROW_B + (ks * 8 + t) * 4;
                const char* wln = wl + n * WROW_B + (ks * 8 + t) * 4;
                bh[nt][0] = *(const uint32_t*)(whn);
                bh[nt][1] = *(const uint32_t*)(whn + 16);
                bl[nt][0] = *(const uint32_t*)(wln);
                bl[nt][1] = *(const uint32_t*)(wln + 16);
            }
#pragma unroll
            for (int mt = 0; mt < 2; mt++) {
                const char* xr0 = xs + (tokRow0 + mt * 16 + g) * 256;
                const char* xr1 = xr0 + 8 * 256;
                uint32_t o0 = (((uint32_t)(ks * 8 + t) ^ xorv) << 3);
                uint32_t o4 = (((uint32_t)(ks * 8 + t + 4) ^ xorv) << 3);
                float2 f00 = *(const float2*)(xr0 + o0);
                float2 f10 = *(const float2*)(xr1 + o0);
                float2 f02 = *(const float2*)(xr0 + o4);
                float2 f12 = *(const float2*)(xr1 + o4);
                uint32_t ah[4], al[4];
                split_pair(f00.x, f00.y, ah[0], al[0]);
                split_pair(f10.x, f10.y, ah[1], al[1]);
                split_pair(f02.x, f02.y, ah[2], al[2]);
                split_pair(f12.x, f12.y, ah[3], al[3]);
#pragma unroll
                for (int nt = 0; nt < 4; nt++) {
                    mma_bf16(acc[mt][nt], ah, bh[nt]);
                    mma_bf16(acc[mt][nt], ah, bl[nt]);
                    mma_bf16(acc[mt][nt], al, bh[nt]);
                    mma_bf16(acc[mt][nt], al, bl[nt]);
                }
            }
        }
        __syncthreads();
        if (c + 2 < NCHUNK) issue_chunk(sbase, x, rowBase, c + 2, tid);
    }

    // ---- epilogue: spill logits to smem (reuse pipeline buffers) ----
    __syncthreads();
    float* lt = (float*)smem;               // [128][65]
    float* rstats = lt + BM * 65;           // rmax[128], rinv[128]
#pragma unroll
    for (int mt = 0; mt < 2; mt++) {
#pragma unroll
        for (int nt = 0; nt < 4; nt++) {
            int r0 = tokRow0 + mt * 16 + g;
            int cc = expCol0 + nt * 8 + 2 * t;
            lt[r0 * 65 + cc]           = acc[mt][nt][0];
            lt[r0 * 65 + cc + 1]       = acc[mt][nt][1];
            lt[(r0 + 8) * 65 + cc]     = acc[mt][nt][2];
            lt[(r0 + 8) * 65 + cc + 1] = acc[mt][nt][3];
        }
    }
    __syncthreads();

    if (tid < BM) {
        const float* row = lt + tid * 65;
        float m1 = -1e30f, m2 = -1e30f;
        int i1 = 0, i2 = 0;
#pragma unroll 8
        for (int e = 0; e < NEXP; e++) {
            float v = row[e];
            if (v > m1) { m2 = m1; i2 = i1; m1 = v; i1 = e; }
            else if (v > m2) { m2 = v; i2 = e; }
        }
        float sum = 0.0f;
#pragma unroll 8
        for (int e = 0; e < NEXP; e++) sum += __expf(row[e] - m1);
        rstats[tid] = m1;
        rstats[BM + tid] = 1.0f / sum;

        float e2 = __expf(m2 - m1);
        float dn = 1.0f / (1.0f + e2);
        int gr = rowBase + tid;
        out_w[gr * TOPK + 0] = dn;
        out_w[gr * TOPK + 1] = e2 * dn;
        out_e[gr * TOPK + 0] = (float)i1;
        out_e[gr * TOPK + 1] = (float)i2;
    }
    __syncthreads();

    for (int i = tid; i < BM * NEXP; i += THREADS) {
        int r = i >> 6, cc = i & 63;
        out_scores[(size_t)(rowBase + r) * NEXP + cc] =
            __expf(lt[r * 65 + cc] - rstats[r]) * rstats[BM + r];
    }
}

extern "C" void kernel_launch(void* const* d_in, const int* in_sizes, int n_in,
                              void* d_out, int out_size) {
    const float* x = (const float*)d_in[0];   // [N, H] f32
    const float* W = (const float*)d_in[1];   // [E, H] f32

    float* out_scores = (float*)d_out;                      // N*E
    float* out_w      = out_scores + (size_t)NTOK * NEXP;   // N*TOPK
    float* out_e      = out_w + (size_t)NTOK * TOPK;        // N*TOPK

    cudaFuncSetAttribute(router_mma, cudaFuncAttributeMaxDynamicSharedMemorySize, SMEM_B);

    wsplit_kernel<<<(NEXP * HDIM) / 256, 256>>>(W);
    router_mma<<<NTOK / BM, THREADS, SMEM_B>>>(x, out_scores, out_w, out_e);
}

// round 4
// speedup vs baseline: 4.6135x; 1.0372x over previous
#include <cuda_runtime.h>
#include <cuda_bf16.h>
#include <cstdint>

#define NTOK 16384
#define HDIM 4096
#define NEXP 64
#define TOPK 2

#define BM 64
#define BK 64
#define NCHUNK (HDIM / BK)    // 64
#define NSTAGE 3
#define THREADS 256

// x tile: 64 rows x 256B (64 f32), float2 units XOR-swizzled within row
#define XTILE_B (BM * 256)              // 16384
// W tiles: 64 rows x 36 4B-units (32 data + 4 pad) = 144B row
#define WROW_B 144
#define WTILE_B (NEXP * WROW_B)         // 9216
#define OFF_WH XTILE_B
#define OFF_WL (XTILE_B + WTILE_B)
#define STAGE_B (XTILE_B + 2 * WTILE_B) // 34816
#define SMEM_B (NSTAGE * STAGE_B)       // 104448

__device__ __nv_bfloat16 g_Wh[NEXP * HDIM];
__device__ __nv_bfloat16 g_Wl[NEXP * HDIM];

__device__ __forceinline__ uint32_t smem_u32(const void* p) {
    uint32_t a;
    asm("{ .reg .u64 t; cvta.to.shared.u64 t, %1; cvt.u32.u64 %0, t; }" : "=r"(a) : "l"(p));
    return a;
}

__device__ __forceinline__ void cpa16(uint32_t dst, const void* src) {
    asm volatile("cp.async.cg.shared.global [%0], [%1], 16;" :: "r"(dst), "l"(src) : "memory");
}

// split f32 pair into bf16x2 hi + bf16x2 lo (element0 in lo16)
__device__ __forceinline__ void split_pair(float f0, float f1, uint32_t& hi, uint32_t& lo) {
    asm("cvt.rn.bf16x2.f32 %0, %1, %2;" : "=r"(hi) : "f"(f1), "f"(f0));
    float h0 = __uint_as_float(hi << 16);
    float h1 = __uint_as_float(hi & 0xFFFF0000u);
    float l0 = f0 - h0;
    float l1 = f1 - h1;
    asm("cvt.rn.bf16x2.f32 %0, %1, %2;" : "=r"(lo) : "f"(l1), "f"(l0));
}

__device__ __forceinline__ void mma_bf16(float* d, const uint32_t* a, const uint32_t* b) {
    asm volatile(
        "mma.sync.aligned.m16n8k16.row.col.f32.bf16.bf16.f32 "
        "{%0,%1,%2,%3}, {%4,%5,%6,%7}, {%8,%9}, {%0,%1,%2,%3};"
        : "+f"(d[0]), "+f"(d[1]), "+f"(d[2]), "+f"(d[3])
        : "r"(a[0]), "r"(a[1]), "r"(a[2]), "r"(a[3]), "r"(b[0]), "r"(b[1]));
}

__global__ void wsplit_kernel(const float* __restrict__ W) {
    int i = blockIdx.x * blockDim.x + threadIdx.x;
    float w = W[i];
    __nv_bfloat16 h = __float2bfloat16(w);
    g_Wh[i] = h;
    g_Wl[i] = __float2bfloat16(w - __bfloat162float(h));
}

__device__ __forceinline__ void issue_chunk(uint32_t sbase, const float* __restrict__ x,
                                            int rowBase, int c, int tid) {
    const int s = c % NSTAGE;
    const uint32_t stb = sbase + s * STAGE_B;
    const int k0 = c * BK;
#pragma unroll
    for (int j = 0; j < 4; j++) {            // x: 1024 16B units
        int i = tid + j * THREADS;
        int row = i >> 4, q = i & 15;
        uint32_t d = stb + row * 256 + ((((2 * q) ^ ((row & 3) << 2))) << 3);
        cpa16(d, x + (size_t)(rowBase + row) * HDIM + k0 + q * 4);
    }
#pragma unroll
    for (int j = 0; j < 2; j++) {            // Wh + Wl: 512 units each
        int i = tid + j * THREADS;
        int row = i >> 3, q = i & 7;
        cpa16(stb + OFF_WH + row * WROW_B + q * 16, g_Wh + (size_t)row * HDIM + k0 + q * 8);
        cpa16(stb + OFF_WL + row * WROW_B + q * 16, g_Wl + (size_t)row * HDIM + k0 + q * 8);
    }
    asm volatile("cp.async.commit_group;" ::: "memory");
}

__global__ __launch_bounds__(THREADS, 2)
void router_mma(const float* __restrict__ x,
                float* __restrict__ out_scores,
                float* __restrict__ out_w,
                float* __restrict__ out_e) {
    extern __shared__ char smem[];
    const uint32_t sbase = smem_u32(smem);
    const int tid = threadIdx.x;
    const int lane = tid & 31;
    const int wid = tid >> 5;
    const int g = lane >> 2;        // 0..7
    const int t = lane & 3;         // 0..3
    const int wExp = wid & 1;       // expert half
    const int wTok = wid >> 1;      // token quarter
    const int rowBase = blockIdx.x * BM;
    const int tokRow0 = wTok * 16;
    const int expCol0 = wExp * 32;
    const uint32_t xorv = (uint32_t)((g & 3) << 2);

    float acc[4][4] = {};

    issue_chunk(sbase, x, rowBase, 0, tid);
    issue_chunk(sbase, x, rowBase, 1, tid);

    for (int c = 0; c < NCHUNK; c++) {
        const int s = c % NSTAGE;
        // issue the next chunk FIRST, then wait for chunk c
        if (c + 2 < NCHUNK) {
            issue_chunk(sbase, x, rowBase, c + 2, tid);
            asm volatile("cp.async.wait_group 2;" ::: "memory");
        } else if (c + 1 < NCHUNK) {
            asm volatile("cp.async.wait_group 1;" ::: "memory");
        } else {
            asm volatile("cp.async.wait_group 0;" ::: "memory");
        }
        __syncthreads();

        const char* st = smem + s * STAGE_B;
        const char* xs = st;
        const char* wh = st + OFF_WH;
        const char* wl = st + OFF_WL;

#pragma unroll
        for (int ks = 0; ks < 4; ks++) {
            // B fragments (W hi/lo, conflict-free stride-36)
            uint32_t bh[4][2], bl[4][2];
#pragma unroll
            for (int nt = 0; nt < 4; nt++) {
                int n = expCol0 + nt * 8 + g;
                const char* whn = wh + n * WROW_B + (ks * 8 + t) * 4;
                const char* wln = wl + n * WROW_B + (ks * 8 + t) * 4;
                bh[nt][0] = *(const uint32_t*)(whn);
                bh[nt][1] = *(const uint32_t*)(whn + 16);
                bl[nt][0] = *(const uint32_t*)(wln);
                bl[nt][1] = *(const uint32_t*)(wln + 16);
            }
            const char* xr0 = xs + (tokRow0 + g) * 256;
            const char* xr1 = xr0 + 8 * 256;
            uint32_t o0 = (((uint32_t)(ks * 8 + t) ^ xorv) << 3);
            uint32_t o4 = (((uint32_t)(ks * 8 + t + 4) ^ xorv) << 3);
            float2 f00 = *(const float2*)(xr0 + o0);
            float2 f10 = *(const float2*)(xr1 + o0);
            float2 f02 = *(const float2*)(xr0 + o4);
            float2 f12 = *(const float2*)(xr1 + o4);
            uint32_t ah[4], al[4];
            split_pair(f00.x, f00.y, ah[0], al[0]);
            split_pair(f10.x, f10.y, ah[1], al[1]);
            split_pair(f02.x, f02.y, ah[2], al[2]);
            split_pair(f12.x, f12.y, ah[3], al[3]);
#pragma unroll
            for (int nt = 0; nt < 4; nt++) {
                mma_bf16(acc[nt], ah, bh[nt]);   // hi*hi
                mma_bf16(acc[nt], ah, bl[nt]);   // hi*lo
                mma_bf16(acc[nt], al, bh[nt]);   // lo*hi  (lo*lo dropped: ~2^-17)
            }
        }
        __syncthreads();
    }

    // ---- epilogue: spill logits to smem (reuse pipeline buffers) ----
    float* lt = (float*)smem;               // [64][65]
    float* rstats = lt + BM * 65;           // rmax[64], rinv[64]
#pragma unroll
    for (int nt = 0; nt < 4; nt++) {
        int r0 = tokRow0 + g;
        int cc = expCol0 + nt * 8 + 2 * t;
        lt[r0 * 65 + cc]           = acc[nt][0];
        lt[r0 * 65 + cc + 1]       = acc[nt][1];
        lt[(r0 + 8) * 65 + cc]     = acc[nt][2];
        lt[(r0 + 8) * 65 + cc + 1] = acc[nt][3];
    }
    __syncthreads();

    if (tid < BM) {
        const float* row = lt + tid * 65;
        float m1 = -1e30f, m2 = -1e30f;
        int i1 = 0, i2 = 0;
#pragma unroll 8
        for (int e = 0; e < NEXP; e++) {
            float v = row[e];
            if (v > m1) { m2 = m1; i2 = i1; m1 = v; i1 = e; }
            else if (v > m2) { m2 = v; i2 = e; }
        }
        float sum = 0.0f;
#pragma unroll 8
        for (int e = 0; e < NEXP; e++) sum += __expf(row[e] - m1);
        rstats[tid] = m1;
        rstats[BM + tid] = 1.0f / sum;

        float e2 = __expf(m2 - m1);
        float dn = 1.0f / (1.0f + e2);
        int gr = rowBase + tid;
        out_w[gr * TOPK + 0] = dn;
        out_w[gr * TOPK + 1] = e2 * dn;
        out_e[gr * TOPK + 0] = (float)i1;
        out_e[gr * TOPK + 1] = (float)i2;
    }
    __syncthreads();

    for (int i = tid; i < BM * NEXP; i += THREADS) {
        int r = i >> 6, cc = i & 63;
        out_scores[(size_t)(rowBase + r) * NEXP + cc] =
            __expf(lt[r * 65 + cc] - rstats[r]) * rstats[BM + r];
    }
}

extern "C" void kernel_launch(void* const* d_in, const int* in_sizes, int n_in,
                              void* d_out, int out_size) {
    const float* x = (const float*)d_in[0];   // [N, H] f32
    const float* W = (const float*)d_in[1];   // [E, H] f32

    float* out_scores = (float*)d_out;                      // N*E
    float* out_w      = out_scores + (size_t)NTOK * NEXP;   // N*TOPK
    float* out_e      = out_w + (size_t)NTOK * TOPK;        // N*TOPK

    cudaFuncSetAttribute(router_mma, cudaFuncAttributeMaxDynamicSharedMemorySize, SMEM_B);

    wsplit_kernel<<<(NEXP * HDIM) / 256, 256>>>(W);
    router_mma<<<NTOK / BM, THREADS, SMEM_B>>>(x, out_scores, out_w, out_e);
}

// round 5
// speedup vs baseline: 5.1629x; 1.1191x over previous
#include <cuda_runtime.h>
#include <cuda_bf16.h>
#include <cstdint>

#define NTOK 16384
#define HDIM 4096
#define NEXP 64
#define TOPK 2

#define BM 128
#define BK 64
#define NCHUNK (HDIM / BK)    // 64
#define NSTAGE 4
#define THREADS 256

// x tile: 128 rows x 256B (64 f32), 8B units XOR-swizzled within row
#define XTILE_B (BM * 256)              // 32768
// W tiles: 64 rows x 144B (128B data + 16B pad)
#define WROW_B 144
#define WTILE_B (NEXP * WROW_B)         // 9216
#define OFF_WH XTILE_B
#define OFF_WL (XTILE_B + WTILE_B)
#define STAGE_B (XTILE_B + 2 * WTILE_B) // 51200
#define SMEM_B (NSTAGE * STAGE_B)       // 204800

__device__ __nv_bfloat16 g_Wh[NEXP * HDIM];
__device__ __nv_bfloat16 g_Wl[NEXP * HDIM];

__device__ __forceinline__ uint32_t smem_u32(const void* p) {
    uint32_t a;
    asm("{ .reg .u64 t; cvta.to.shared.u64 t, %1; cvt.u32.u64 %0, t; }" : "=r"(a) : "l"(p));
    return a;
}

__device__ __forceinline__ void cpa16(uint32_t dst, const void* src) {
    asm volatile("cp.async.cg.shared.global [%0], [%1], 16;" :: "r"(dst), "l"(src) : "memory");
}

__device__ __forceinline__ void ldm4(uint32_t addr, uint32_t* r) {
    asm volatile("ldmatrix.sync.aligned.m8n8.x4.shared.b16 {%0,%1,%2,%3}, [%4];"
                 : "=r"(r[0]), "=r"(r[1]), "=r"(r[2]), "=r"(r[3]) : "r"(addr));
}

// split f32 pair into bf16x2 hi + bf16x2 lo (element0 in lo16)
__device__ __forceinline__ void split_pair(float f0, float f1, uint32_t& hi, uint32_t& lo) {
    asm("cvt.rn.bf16x2.f32 %0, %1, %2;" : "=r"(hi) : "f"(f1), "f"(f0));
    float h0 = __uint_as_float(hi << 16);
    float h1 = __uint_as_float(hi & 0xFFFF0000u);
    float l0 = f0 - h0;
    float l1 = f1 - h1;
    asm("cvt.rn.bf16x2.f32 %0, %1, %2;" : "=r"(lo) : "f"(l1), "f"(l0));
}

__device__ __forceinline__ void mma_bf16(float* d, const uint32_t* a, const uint32_t* b) {
    asm volatile(
        "mma.sync.aligned.m16n8k16.row.col.f32.bf16.bf16.f32 "
        "{%0,%1,%2,%3}, {%4,%5,%6,%7}, {%8,%9}, {%0,%1,%2,%3};"
        : "+f"(d[0]), "+f"(d[1]), "+f"(d[2]), "+f"(d[3])
        : "r"(a[0]), "r"(a[1]), "r"(a[2]), "r"(a[3]), "r"(b[0]), "r"(b[1]));
}

__global__ void wsplit_kernel(const float* __restrict__ W) {
    int i = blockIdx.x * blockDim.x + threadIdx.x;
    float w = W[i];
    __nv_bfloat16 h = __float2bfloat16(w);
    g_Wh[i] = h;
    g_Wl[i] = __float2bfloat16(w - __bfloat162float(h));
}

__device__ __forceinline__ void issue_chunk(uint32_t sbase, const float* __restrict__ x,
                                            int rowBase, int c, int tid) {
    const int s = c & (NSTAGE - 1);
    const uint32_t stb = sbase + s * STAGE_B;
    const int k0 = c * BK;
#pragma unroll
    for (int j = 0; j < 8; j++) {            // x: 2048 16B units
        int i = tid + j * THREADS;
        int row = i >> 4, q = i & 15;
        uint32_t d = stb + row * 256 + ((((2 * q) ^ ((row & 7) << 2))) << 3);
        cpa16(d, x + (size_t)(rowBase + row) * HDIM + k0 + q * 4);
    }
#pragma unroll
    for (int j = 0; j < 2; j++) {            // Wh + Wl: 512 units each
        int i = tid + j * THREADS;
        int row = i >> 3, q = i & 7;
        cpa16(stb + OFF_WH + row * WROW_B + q * 16, g_Wh + (size_t)row * HDIM + k0 + q * 8);
        cpa16(stb + OFF_WL + row * WROW_B + q * 16, g_Wl + (size_t)row * HDIM + k0 + q * 8);
    }
    asm volatile("cp.async.commit_group;" ::: "memory");
}

__global__ __launch_bounds__(THREADS, 1)
void router_mma(const float* __restrict__ x,
                float* __restrict__ out_scores,
                float* __restrict__ out_w,
                float* __restrict__ out_e) {
    extern __shared__ char smem[];
    const uint32_t sbase = smem_u32(smem);
    const int tid = threadIdx.x;
    const int lane = tid & 31;
    const int wid = tid >> 5;
    const int g = lane >> 2;        // 0..7
    const int t = lane & 3;         // 0..3
    const int wExp = wid & 1;       // expert half (32 experts)
    const int wTok = wid >> 1;      // token quarter (32 rows)
    const int rowBase = blockIdx.x * BM;
    const int tokRow0 = wTok * 32;
    const int expCol0 = wExp * 32;

    // ldmatrix per-lane address offset (within a W tile), j selects nt pair
    const int mtx = lane >> 3;      // matrix index 0..3
    const int rr = lane & 7;
    const uint32_t w_lane_off =
        (uint32_t)((expCol0 + (mtx >> 1) * 8 + rr) * WROW_B + (mtx & 1) * 16);

    float acc[2][4][4] = {};

    issue_chunk(sbase, x, rowBase, 0, tid);
    issue_chunk(sbase, x, rowBase, 1, tid);
    issue_chunk(sbase, x, rowBase, 2, tid);

    for (int c = 0; c < NCHUNK; c++) {
        const int s = c & (NSTAGE - 1);
        if (c <= NCHUNK - 3) {
            asm volatile("cp.async.wait_group 2;" ::: "memory");
        } else if (c == NCHUNK - 2) {
            asm volatile("cp.async.wait_group 1;" ::: "memory");
        } else {
            asm volatile("cp.async.wait_group 0;" ::: "memory");
        }
        __syncthreads();   // single barrier: stage-c visible; stage (c+3)%4 free

        if (c + 3 < NCHUNK) issue_chunk(sbase, x, rowBase, c + 3, tid);

        const uint32_t stb = sbase + s * STAGE_B;
        const char* xs = smem + s * STAGE_B;
        const uint32_t whA = stb + OFF_WH + w_lane_off;   // j=0 (nt 0,1)
        const uint32_t wlA = stb + OFF_WL + w_lane_off;

#pragma unroll
        for (int ks = 0; ks < 4; ks++) {
            // ---- B fragments via ldmatrix.x4: 2 hi + 2 lo ----
            uint32_t bh[8], bl[8];   // [nt*2 + reg]
            ldm4(whA + ks * 32, bh);                       // nt 0,1
            ldm4(whA + 16 * WROW_B + ks * 32, bh + 4);     // nt 2,3
            ldm4(wlA + ks * 32, bl);
            ldm4(wlA + 16 * WROW_B + ks * 32, bl + 4);

            // ---- A fragments: 2 mt tiles, split f32 -> bf16 hi/lo ----
            uint32_t u0 = ((uint32_t)(ks * 8 + t) ^ ((uint32_t)g << 2)) << 3;
            uint32_t u4 = u0 ^ 32;
#pragma unroll
            for (int mt = 0; mt < 2; mt++) {
                const char* xr0 = xs + (tokRow0 + mt * 16 + g) * 256;
                const char* xr1 = xr0 + 8 * 256;
                float2 f00 = *(const float2*)(xr0 + u0);
                float2 f10 = *(const float2*)(xr1 + u0);
                float2 f02 = *(const float2*)(xr0 + u4);
                float2 f12 = *(const float2*)(xr1 + u4);
                uint32_t ah[4], al[4];
                split_pair(f00.x, f00.y, ah[0], al[0]);
                split_pair(f10.x, f10.y, ah[1], al[1]);
                split_pair(f02.x, f02.y, ah[2], al[2]);
                split_pair(f12.x, f12.y, ah[3], al[3]);
#pragma unroll
                for (int nt = 0; nt < 4; nt++) {
                    mma_bf16(acc[mt][nt], ah, bh + nt * 2);   // hi*hi
                    mma_bf16(acc[mt][nt], ah, bl + nt * 2);   // hi*lo
                    mma_bf16(acc[mt][nt], al, bh + nt * 2);   // lo*hi
                }
            }
        }
    }

    // ---- epilogue: spill logits to smem (stage 0/1 regions are long dead) ----
    __syncthreads();
    float* lt = (float*)smem;               // [128][65]
    float* rstats = lt + BM * 65;
#pragma unroll
    for (int mt = 0; mt < 2; mt++) {
#pragma unroll
        for (int nt = 0; nt < 4; nt++) {
            int r0 = tokRow0 + mt * 16 + g;
            int cc = expCol0 + nt * 8 + 2 * t;
            lt[r0 * 65 + cc]           = acc[mt][nt][0];
            lt[r0 * 65 + cc + 1]       = acc[mt][nt][1];
            lt[(r0 + 8) * 65 + cc]     = acc[mt][nt][2];
            lt[(r0 + 8) * 65 + cc + 1] = acc[mt][nt][3];
        }
    }
    __syncthreads();

    if (tid < BM) {
        const float* row = lt + tid * 65;
        float m1 = -1e30f, m2 = -1e30f;
        int i1 = 0, i2 = 0;
#pragma unroll 8
        for (int e = 0; e < NEXP; e++) {
            float v = row[e];
            if (v > m1) { m2 = m1; i2 = i1; m1 = v; i1 = e; }
            else if (v > m2) { m2 = v; i2 = e; }
        }
        float sum = 0.0f;
#pragma unroll 8
        for (int e = 0; e < NEXP; e++) sum += __expf(row[e] - m1);
        rstats[tid] = m1;
        rstats[BM + tid] = 1.0f / sum;

        float e2 = __expf(m2 - m1);
        float dn = 1.0f / (1.0f + e2);
        int gr = rowBase + tid;
        out_w[gr * TOPK + 0] = dn;
        out_w[gr * TOPK + 1] = e2 * dn;
        out_e[gr * TOPK + 0] = (float)i1;
        out_e[gr * TOPK + 1] = (float)i2;
    }
    __syncthreads();

    for (int i = tid; i < BM * NEXP; i += THREADS) {
        int r = i >> 6, cc = i & 63;
        out_scores[(size_t)(rowBase + r) * NEXP + cc] =
            __expf(lt[r * 65 + cc] - rstats[r]) * rstats[BM + r];
    }
}

extern "C" void kernel_launch(void* const* d_in, const int* in_sizes, int n_in,
                              void* d_out, int out_size) {
    const float* x = (const float*)d_in[0];   // [N, H] f32
    const float* W = (const float*)d_in[1];   // [E, H] f32

    float* out_scores = (float*)d_out;                      // N*E
    float* out_w      = out_scores + (size_t)NTOK * NEXP;   // N*TOPK
    float* out_e      = out_w + (size_t)NTOK * TOPK;        // N*TOPK

    cudaFuncSetAttribute(router_mma, cudaFuncAttributeMaxDynamicSharedMemorySize, SMEM_B);

    wsplit_kernel<<<(NEXP * HDIM) / 256, 256>>>(W);
    router_mma<<<NTOK / BM, THREADS, SMEM_B>>>(x, out_scores, out_w, out_e);
}